// round 15
// baseline (speedup 1.0000x reference)
#include <cuda_runtime.h>
#include <cuda_bf16.h>
#include <cstdint>

#define M_DIM 64
#define K_DIM 8192
#define N_DIM 8192
#define KBLK  16
#define NTILE 128
#define KSPLIT 4
#define KC    32
#define ITERS ((K_DIM / KSPLIT) / KC)   /* 64 */
#define THREADS 256
#define WSTRIDE 48
#define MAGIC_I 0x4B400000
#define MAGIC_F 12582912.0f

__device__ float  g_scratch[KSPLIT * M_DIM * N_DIM];  // 8 MB fp32 partial slabs
__device__ int8_t g_xi8[M_DIM * K_DIM];               // x as int8 (2x values)

__constant__ int c_ilut[16] = { 0, 1, 2, 3, 4, 6, 8, 12,
                                0,-1,-2,-3,-4,-6,-8,-12};

#define DP4A(acc, a, b) \
    asm("dp4a.s32.s32 %0, %1, %2, %0;" : "+r"(acc) : "r"(a), "r"(b))

__global__ void prep_kernel(const int* __restrict__ x) {
    int t    = blockIdx.x * blockDim.x + threadIdx.x;
    int lane = threadIdx.x & 31;
    int ilut = c_ilut[lane & 15];
    int4 c = ((const int4*)x)[t];
    int v0 = __shfl_sync(0xffffffffu, ilut, c.x & 15);
    int v1 = __shfl_sync(0xffffffffu, ilut, c.y & 15);
    int v2 = __shfl_sync(0xffffffffu, ilut, c.z & 15);
    int v3 = __shfl_sync(0xffffffffu, ilut, c.w & 15);
    unsigned t01 = __byte_perm((unsigned)v0, (unsigned)v1, 0x0040);
    unsigned t23 = __byte_perm((unsigned)v2, (unsigned)v3, 0x0040);
    ((unsigned*)g_xi8)[t] = __byte_perm(t01, t23, 0x5410);
}

// ---------------------------------------------------------------------------
// Hybrid exact GEMM: mma.sync CTAs (n-tiles 0..23) + dp4a CTAs (24..63).
// Residues {0,3,5} (mma) vs +4 partners {4,7,1}: disjoint -> every SM pairs
// one mma CTA with one dp4a CTA (tensor || fma overlap).
// ---------------------------------------------------------------------------
__global__ void __launch_bounds__(THREADS, 2)
gemm_kernel(const int* __restrict__ w, const float* __restrict__ wsc,
            const float* __restrict__ xsc) {
    __shared__ int8_t sW8[2][NTILE * WSTRIDE];
    __shared__ int8_t sX8[2][M_DIM * WSTRIDE];
    __shared__ float  sWS[2][NTILE * 2];     // [row*2 + block]
    __shared__ float  sXS[2][M_DIM * 2];

    const int tid  = threadIdx.x;
    const int lane = tid & 31;
    const int warp = tid >> 5;
    const int ilut = c_ilut[lane & 15];

    const int bid = blockIdx.x;
    const int r8  = bid & 7;
    const int base = bid >> 3;
    const bool is_mma = (r8 == 0) | (r8 == 3) | (r8 == 5);
    int bn, ksp;
    if (is_mma) {
        int t = (r8 == 0) ? 0 : (r8 == 3) ? 1 : 2;
        int idx = base * 3 + t;
        bn = idx >> 2; ksp = idx & 3;
    } else {
        int t = (r8 == 1) ? 0 : (r8 == 2) ? 1 : (r8 == 4) ? 2 : (r8 == 6) ? 3 : 4;
        int idx = base * 5 + t;
        bn = 24 + (idx >> 2); ksp = idx & 3;
    }
    const int k0 = ksp * (K_DIM / KSPLIT);

    int4  wc[4];
    uint2 xc;
    float wsv, xsv;

    #define LOAD_STAGE(it)                                                         \
    {                                                                              \
        const int kb = k0 + (it) * KC;                                             \
        _Pragma("unroll")                                                          \
        for (int t = 0; t < 4; ++t) {                                              \
            int p = tid + t * 256;                                                 \
            int row = p >> 3, kc4 = p & 7;                                         \
            wc[t] = *(const int4*)(w + (long)(bn * NTILE + row) * K_DIM            \
                                     + kb + kc4 * 4);                              \
        }                                                                          \
        { int row = tid >> 2, seg = tid & 3;                                       \
          xc = *(const uint2*)(g_xi8 + row * K_DIM + kb + seg * 8); }              \
        { int row = tid >> 1, b = tid & 1;                                         \
          wsv = wsc[(bn * NTILE + row) * (K_DIM / KBLK) + (kb >> 4) + b]; }        \
        if (tid < 128) {                                                           \
            int row = tid >> 1, b = tid & 1;                                       \
            xsv = xsc[row * (K_DIM / KBLK) + (kb >> 4) + b];                       \
        }                                                                          \
    }

    #define STORE_STAGE(buf)                                                      \
    {                                                                              \
        _Pragma("unroll")                                                          \
        for (int t = 0; t < 4; ++t) {                                              \
            int p = tid + t * 256;                                                 \
            int row = p >> 3, kc4 = p & 7;                                         \
            int v0 = __shfl_sync(0xffffffffu, ilut, wc[t].x & 15);                 \
            int v1 = __shfl_sync(0xffffffffu, ilut, wc[t].y & 15);                 \
            int v2 = __shfl_sync(0xffffffffu, ilut, wc[t].z & 15);                 \
            int v3 = __shfl_sync(0xffffffffu, ilut, wc[t].w & 15);                 \
            unsigned t01 = __byte_perm((unsigned)v0, (unsigned)v1, 0x0040);        \
            unsigned t23 = __byte_perm((unsigned)v2, (unsigned)v3, 0x0040);        \
            *(unsigned*)(&sW8[buf][row * WSTRIDE + kc4 * 4]) =                     \
                __byte_perm(t01, t23, 0x5410);                                     \
        }                                                                          \
        { int row = tid >> 2, seg = tid & 3;                                       \
          *(uint2*)(&sX8[buf][row * WSTRIDE + seg * 8]) = xc; }                    \
        { int row = tid >> 1, b = tid & 1; sWS[buf][row * 2 + b] = wsv; }          \
        if (tid < 128) {                                                           \
            int row = tid >> 1, b = tid & 1;                                       \
            sXS[buf][row * 2 + b] = xsv;                                           \
        }                                                                          \
    }

    unsigned long long magic2;
    asm("mov.b64 %0, {%1, %1};" : "=l"(magic2) : "f"(-MAGIC_F));

    if (is_mma) {
        // ---------------- tensor-pipe path (round-9/12 proven math) ---------
        const int g  = lane >> 2;
        const int tg = lane & 3;
        const int wr = warp * 16;
        unsigned long long accp[8][2];
        #pragma unroll
        for (int j = 0; j < 8; ++j) { accp[j][0] = 0ull; accp[j][1] = 0ull; }

        LOAD_STAGE(0);
        for (int it = 0; it < ITERS; ++it) {
            const int buf = it & 1;
            STORE_STAGE(buf);
            __syncthreads();
            if (it + 1 < ITERS) LOAD_STAGE(it + 1);

            const int8_t* Wb = &sW8[buf][wr * WSTRIDE];
            const int8_t* Xb = &sX8[buf][0];
            unsigned a0[2], a1[2];
            unsigned long long wdup[2], w8dup[2];
            #pragma unroll
            for (int b = 0; b < 2; ++b) {
                a0[b] = *(const unsigned*)(Wb + (g    ) * WSTRIDE + b * 16 + tg * 4);
                a1[b] = *(const unsigned*)(Wb + (g + 8) * WSTRIDE + b * 16 + tg * 4);
                float wsg  = sWS[buf][(wr + g    ) * 2 + b];
                float wsg8 = sWS[buf][(wr + 8 + g) * 2 + b];
                asm("mov.b64 %0, {%1, %1};" : "=l"(wdup[b])
                    : "r"(__float_as_uint(wsg)));
                asm("mov.b64 %0, {%1, %1};" : "=l"(w8dup[b])
                    : "r"(__float_as_uint(wsg8)));
            }
            #pragma unroll
            for (int j = 0; j < 8; ++j) {
                float4 xsq = *(const float4*)&sXS[buf][(j * 8 + 2 * tg) * 2];
                unsigned long long xsp[2];
                asm("mov.b64 %0, {%1, %2};" : "=l"(xsp[0])
                    : "r"(__float_as_uint(xsq.x)), "r"(__float_as_uint(xsq.z)));
                asm("mov.b64 %0, {%1, %2};" : "=l"(xsp[1])
                    : "r"(__float_as_uint(xsq.y)), "r"(__float_as_uint(xsq.w)));
                #pragma unroll
                for (int b = 0; b < 2; ++b) {
                    unsigned bf = *(const unsigned*)(Xb + (j * 8 + g) * WSTRIDE
                                                     + b * 16 + tg * 4);
                    int d0, d1, d2, d3;
                    asm volatile(
                        "mma.sync.aligned.m16n8k16.row.col.s32.s8.s8.s32 "
                        "{%0,%1,%2,%3}, {%4,%5}, {%6}, {%7,%8,%9,%10};\n"
                        : "=r"(d0), "=r"(d1), "=r"(d2), "=r"(d3)
                        : "r"(a0[b]), "r"(a1[b]), "r"(bf),
                          "r"(0), "r"(0), "r"(0), "r"(0));
                    unsigned long long sc01, sc23, p01, p23, f01, f23;
                    asm("mul.rn.f32x2 %0, %1, %2;" : "=l"(sc01)
                        : "l"(xsp[b]), "l"(wdup[b]));
                    asm("mul.rn.f32x2 %0, %1, %2;" : "=l"(sc23)
                        : "l"(xsp[b]), "l"(w8dup[b]));
                    asm("mov.b64 %0, {%1, %2};" : "=l"(p01)
                        : "r"(d0 + MAGIC_I), "r"(d1 + MAGIC_I));
                    asm("mov.b64 %0, {%1, %2};" : "=l"(p23)
                        : "r"(d2 + MAGIC_I), "r"(d3 + MAGIC_I));
                    asm("add.rn.f32x2 %0, %1, %2;" : "=l"(f01) : "l"(p01), "l"(magic2));
                    asm("add.rn.f32x2 %0, %1, %2;" : "=l"(f23) : "l"(p23), "l"(magic2));
                    asm("fma.rn.f32x2 %0, %1, %2, %0;" : "+l"(accp[j][0])
                        : "l"(f01), "l"(sc01));
                    asm("fma.rn.f32x2 %0, %1, %2, %0;" : "+l"(accp[j][1])
                        : "l"(f23), "l"(sc23));
                }
            }
        }
        float* S = g_scratch + ksp * (M_DIM * N_DIM);
        const int nbase = bn * NTILE + wr + g;
        #pragma unroll
        for (int j = 0; j < 8; ++j) {
            const int m0 = j * 8 + tg * 2;
            unsigned c0, c1, c2, c3;
            asm("mov.b64 {%0, %1}, %2;" : "=r"(c0), "=r"(c1) : "l"(accp[j][0]));
            asm("mov.b64 {%0, %1}, %2;" : "=r"(c2), "=r"(c3) : "l"(accp[j][1]));
            S[(m0    ) * N_DIM + nbase    ] = __uint_as_float(c0);
            S[(m0 + 1) * N_DIM + nbase    ] = __uint_as_float(c1);
            S[(m0    ) * N_DIM + nbase + 8] = __uint_as_float(c2);
            S[(m0 + 1) * N_DIM + nbase + 8] = __uint_as_float(c3);
        }
    } else {
        // ---------------- fma-pipe path (dp4a, same exact math) -------------
        // thread owns n = bn*128 + lane + 32q (q=0..3), m = warp*8 + mi (0..7)
        const int mg = warp * 8;
        unsigned long long accp[8][2];   // [mi][(q0,q1) | (q2,q3)]
        #pragma unroll
        for (int j = 0; j < 8; ++j) { accp[j][0] = 0ull; accp[j][1] = 0ull; }

        LOAD_STAGE(0);
        for (int it = 0; it < ITERS; ++it) {
            const int buf = it & 1;
            STORE_STAGE(buf);
            __syncthreads();
            if (it + 1 < ITERS) LOAD_STAGE(it + 1);

            const int8_t* Wb = &sX8[buf][0];   // placeholder silencer (unused)
            (void)Wb;
            // per-q W scales, both blocks (LDS.64, conflict-free per phase)
            float2 ws2[4];
            #pragma unroll
            for (int q = 0; q < 4; ++q)
                ws2[q] = *(const float2*)&sWS[buf][(lane + 32 * q) * 2];

            #pragma unroll
            for (int b = 0; b < 2; ++b) {
                uint4 wv[4];
                #pragma unroll
                for (int q = 0; q < 4; ++q)
                    wv[q] = *(const uint4*)(&sW8[buf][(lane + 32 * q) * WSTRIDE
                                                      + b * 16]);
                unsigned long long ws01, ws23;
                float w0 = b ? ws2[0].y : ws2[0].x;
                float w1 = b ? ws2[1].y : ws2[1].x;
                float w2 = b ? ws2[2].y : ws2[2].x;
                float w3 = b ? ws2[3].y : ws2[3].x;
                asm("mov.b64 %0, {%1, %2};" : "=l"(ws01)
                    : "r"(__float_as_uint(w0)), "r"(__float_as_uint(w1)));
                asm("mov.b64 %0, {%1, %2};" : "=l"(ws23)
                    : "r"(__float_as_uint(w2)), "r"(__float_as_uint(w3)));

                #pragma unroll
                for (int mi = 0; mi < 8; ++mi) {
                    uint4 xv = *(const uint4*)(&sX8[buf][(mg + mi) * WSTRIDE
                                                         + b * 16]);
                    float2 xs2 = *(const float2*)&sXS[buf][(mg + mi) * 2];
                    float xsb = b ? xs2.y : xs2.x;
                    unsigned long long xsd;
                    asm("mov.b64 %0, {%1, %1};" : "=l"(xsd)
                        : "r"(__float_as_uint(xsb)));
                    int d0 = 0, d1 = 0, d2 = 0, d3 = 0;
                    DP4A(d0, wv[0].x, xv.x); DP4A(d0, wv[0].y, xv.y);
                    DP4A(d0, wv[0].z, xv.z); DP4A(d0, wv[0].w, xv.w);
                    DP4A(d1, wv[1].x, xv.x); DP4A(d1, wv[1].y, xv.y);
                    DP4A(d1, wv[1].z, xv.z); DP4A(d1, wv[1].w, xv.w);
                    DP4A(d2, wv[2].x, xv.x); DP4A(d2, wv[2].y, xv.y);
                    DP4A(d2, wv[2].z, xv.z); DP4A(d2, wv[2].w, xv.w);
                    DP4A(d3, wv[3].x, xv.x); DP4A(d3, wv[3].y, xv.y);
                    DP4A(d3, wv[3].z, xv.z); DP4A(d3, wv[3].w, xv.w);
                    unsigned long long p01, p23, f01, f23, s01, s23;
                    asm("mov.b64 %0, {%1, %2};" : "=l"(p01)
                        : "r"(d0 + MAGIC_I), "r"(d1 + MAGIC_I));
                    asm("mov.b64 %0, {%1, %2};" : "=l"(p23)
                        : "r"(d2 + MAGIC_I), "r"(d3 + MAGIC_I));
                    asm("add.rn.f32x2 %0, %1, %2;" : "=l"(f01) : "l"(p01), "l"(magic2));
                    asm("add.rn.f32x2 %0, %1, %2;" : "=l"(f23) : "l"(p23), "l"(magic2));
                    asm("mul.rn.f32x2 %0, %1, %2;" : "=l"(s01) : "l"(ws01), "l"(xsd));
                    asm("mul.rn.f32x2 %0, %1, %2;" : "=l"(s23) : "l"(ws23), "l"(xsd));
                    asm("fma.rn.f32x2 %0, %1, %2, %0;" : "+l"(accp[mi][0])
                        : "l"(f01), "l"(s01));
                    asm("fma.rn.f32x2 %0, %1, %2, %0;" : "+l"(accp[mi][1])
                        : "l"(f23), "l"(s23));
                }
            }
        }
        float* S = g_scratch + ksp * (M_DIM * N_DIM);
        const int n0 = bn * NTILE + lane;
        #pragma unroll
        for (int mi = 0; mi < 8; ++mi) {
            const int m = mg + mi;
            unsigned c0, c1, c2, c3;
            asm("mov.b64 {%0, %1}, %2;" : "=r"(c0), "=r"(c1) : "l"(accp[mi][0]));
            asm("mov.b64 {%0, %1}, %2;" : "=r"(c2), "=r"(c3) : "l"(accp[mi][1]));
            S[m * N_DIM + n0     ] = __uint_as_float(c0);
            S[m * N_DIM + n0 + 32] = __uint_as_float(c1);
            S[m * N_DIM + n0 + 64] = __uint_as_float(c2);
            S[m * N_DIM + n0 + 96] = __uint_as_float(c3);
        }
    }
    #undef LOAD_STAGE
    #undef STORE_STAGE
}

__global__ void finalize_kernel(const float* __restrict__ g1,
                                const float* __restrict__ g2,
                                const float* __restrict__ bias,
                                float* __restrict__ out) {
    int idx = blockIdx.x * blockDim.x + threadIdx.x;
    if (idx >= M_DIM * N_DIM) return;
    const float g = g1[0] * g2[0] * 0.25f;
    const int n = idx & (N_DIM - 1);
    float s = 0.f;
    #pragma unroll
    for (int t = 0; t < KSPLIT; ++t)
        s += g_scratch[idx + t * (M_DIM * N_DIM)];
    float v = fmaf(s, g, bias[n]);
    out[idx] = __bfloat162float(__float2bfloat16(v));
}

extern "C" void kernel_launch(void* const* d_in, const int* in_sizes, int n_in,
                              void* d_out, int out_size) {
    const int*   x    = nullptr;
    const float* xs   = nullptr;
    const int*   wgt  = nullptr;
    const float* wsc  = nullptr;
    const float* bias = nullptr;
    const float* gA   = nullptr;
    const float* gB   = nullptr;

    for (int pass = 0; pass < 2 && !wgt; ++pass) {
        const int mul = (pass == 0) ? 1 : 4;
        x = nullptr; xs = nullptr; wgt = nullptr; wsc = nullptr;
        bias = nullptr; gA = nullptr; gB = nullptr;
        for (int i = 0; i < n_in; ++i) {
            long sz = (long)in_sizes[i];
            if      (sz == (long)M_DIM * K_DIM * mul)          x    = (const int*)  d_in[i];
            else if (sz == (long)M_DIM * (K_DIM/KBLK) * mul)   xs   = (const float*)d_in[i];
            else if (sz == (long)N_DIM * K_DIM * mul)          wgt  = (const int*)  d_in[i];
            else if (sz == (long)N_DIM * (K_DIM/KBLK) * mul)   wsc  = (const float*)d_in[i];
            else if (sz == (long)N_DIM * mul)                  bias = (const float*)d_in[i];
            else if (sz == 1 * mul) { if (!gA) gA = (const float*)d_in[i];
                                      else     gB = (const float*)d_in[i]; }
        }
    }

    prep_kernel<<<(M_DIM * K_DIM / 4) / THREADS, THREADS>>>(x);
    gemm_kernel<<<256, THREADS>>>(wgt, wsc, xs);
    finalize_kernel<<<(M_DIM * N_DIM) / 256, 256>>>(gA, gB, bias,
                                                    (float*)d_out);
}

// round 16
// speedup vs baseline: 1.3453x; 1.3453x over previous
#include <cuda_runtime.h>
#include <cuda_bf16.h>
#include <cuda_fp16.h>
#include <cstdint>

#define M_DIM 64
#define K_DIM 8192
#define N_DIM 8192
#define KBLK  16
#define NTILE 128
#define KSPLIT 4
#define KC    32
#define ITERS ((K_DIM / KSPLIT) / KC)   /* 64 */
#define THREADS 256
#define STR   40      /* halves per smem row: ldmatrix banks (20r+c)%32 = permutation */

/* dynamic smem (bytes): Wh[2][128][80B] Wl Xh[2][64][80B] Xl */
#define WH_OFF 0
#define WL_OFF 20480
#define XH_OFF 40960
#define XL_OFF 51200
#define SMEM_BYTES 61440

__device__ float  g_scratch[KSPLIT * M_DIM * N_DIM];  // 8 MB fp32 partial slabs
__device__ __half g_xh[M_DIM * K_DIM];   // x hi (scale folded, x4096, fp16-exact)
__device__ __half g_xl[M_DIM * K_DIM];   // x lo correction

__constant__ float c_lut[16] = { 0.f, 0.5f, 1.f, 1.5f, 2.f, 3.f, 4.f, 6.f,
                                -0.f,-0.5f,-1.f,-1.5f,-2.f,-3.f,-4.f,-6.f};

// ---------------------------------------------------------------------------
// Kernel A: x codes -> (xh, xl) fp16, block scale folded.
//   sb = s*4096; sh = sb with mantissa truncated to 8 bits; sl = sb - sh.
//   xh = lut*sh is EXACT in fp16 (<=10-bit significand); xl ~ 2^-8 smaller.
// ---------------------------------------------------------------------------
__global__ void prep_kernel(const int* __restrict__ x, const float* __restrict__ xs) {
    int t    = blockIdx.x * blockDim.x + threadIdx.x;   // < M*K/4
    int lane = threadIdx.x & 31;
    float lutv = c_lut[lane & 15];
    int4 c = ((const int4*)x)[t];
    int k4 = t & (K_DIM / 4 - 1);
    int m  = t >> 11;
    float s  = xs[m * (K_DIM / KBLK) + (k4 >> 2)];
    float sb = s * 4096.0f;
    float sh = __uint_as_float(__float_as_uint(sb) & 0xFFFF8000u);
    float sl = sb - sh;
    float v0 = __shfl_sync(0xffffffffu, lutv, c.x & 15);
    float v1 = __shfl_sync(0xffffffffu, lutv, c.y & 15);
    float v2 = __shfl_sync(0xffffffffu, lutv, c.z & 15);
    float v3 = __shfl_sync(0xffffffffu, lutv, c.w & 15);
    __half2 h0 = __floats2half2_rn(v0 * sh, v1 * sh);
    __half2 h1 = __floats2half2_rn(v2 * sh, v3 * sh);
    __half2 l0 = __floats2half2_rn(v0 * sl, v1 * sl);
    __half2 l1 = __floats2half2_rn(v2 * sl, v3 * sl);
    ((__half2*)g_xh)[t * 2    ] = h0;
    ((__half2*)g_xh)[t * 2 + 1] = h1;
    ((__half2*)g_xl)[t * 2    ] = l0;
    ((__half2*)g_xl)[t * 2 + 1] = l1;
}

// ---------------------------------------------------------------------------
// Kernel B: hi/lo fp16 HMMA GEMM. acc(fp32) += Ah*Bh + Ah*Bl + Al*Bh.
// Grid (N/128, KSPLIT). CTA 256 thr / 8 warps; warp w owns W rows
// [w*16, w*16+16) x all 64 x rows. ldmatrix/mma/epilogue mappings are the
// round-8-validated ones. Zero per-MMA scalar work (scales pre-folded).
// ---------------------------------------------------------------------------
__global__ void __launch_bounds__(THREADS, 2)
gemm_kernel(const int* __restrict__ w, const float* __restrict__ wsc) {
    extern __shared__ char smem[];

    const int tid  = threadIdx.x;
    const int lane = tid & 31;
    const int warp = tid >> 5;
    const int bn   = blockIdx.x;
    const int k0   = blockIdx.y * (K_DIM / KSPLIT);
    const float lutv = c_lut[lane & 15];

    float acc[8][4];
    #pragma unroll
    for (int j = 0; j < 8; ++j)
        #pragma unroll
        for (int q = 0; q < 4; ++q) acc[j][q] = 0.f;

    // staging registers for one K-chunk (KC=32)
    int4  wc[4];    // 128 rows x 32 codes / 256 thr
    float wsv[4];   // block scale per int4
    uint4 xhr, xlr; // 64 rows x 32 halves / 256 thr, hi & lo

    #define LOAD_STAGE(it)                                                         \
    {                                                                              \
        const int kb = k0 + (it) * KC;                                             \
        _Pragma("unroll")                                                          \
        for (int t = 0; t < 4; ++t) {                                              \
            int p = tid + t * 256;                                                 \
            int row = p >> 3, kc4 = p & 7;                                         \
            int grow = bn * NTILE + row;                                           \
            wc[t]  = *(const int4*)(w + (long)grow * K_DIM + kb + kc4 * 4);        \
            wsv[t] = wsc[grow * (K_DIM / KBLK) + (kb >> 4) + (kc4 >> 2)];          \
        }                                                                          \
        {                                                                          \
            int row = tid >> 2, seg = tid & 3;                                     \
            xhr = *(const uint4*)(g_xh + row * K_DIM + kb + seg * 8);              \
            xlr = *(const uint4*)(g_xl + row * K_DIM + kb + seg * 8);              \
        }                                                                          \
    }

    #define STORE_STAGE(buf)                                                       \
    {                                                                              \
        char* WhB = smem + WH_OFF + (buf) * 10240;                                 \
        char* WlB = smem + WL_OFF + (buf) * 10240;                                 \
        char* XhB = smem + XH_OFF + (buf) * 5120;                                  \
        char* XlB = smem + XL_OFF + (buf) * 5120;                                  \
        _Pragma("unroll")                                                          \
        for (int t = 0; t < 4; ++t) {                                              \
            int p = tid + t * 256;                                                 \
            int row = p >> 3, kc4 = p & 7;                                         \
            float sb = wsv[t] * 4096.0f;                                           \
            float sh = __uint_as_float(__float_as_uint(sb) & 0xFFFF8000u);         \
            float sl = sb - sh;                                                    \
            float v0 = __shfl_sync(0xffffffffu, lutv, wc[t].x & 15);               \
            float v1 = __shfl_sync(0xffffffffu, lutv, wc[t].y & 15);               \
            float v2 = __shfl_sync(0xffffffffu, lutv, wc[t].z & 15);               \
            float v3 = __shfl_sync(0xffffffffu, lutv, wc[t].w & 15);               \
            __half2 h0 = __floats2half2_rn(v0 * sh, v1 * sh);                      \
            __half2 h1 = __floats2half2_rn(v2 * sh, v3 * sh);                      \
            __half2 l0 = __floats2half2_rn(v0 * sl, v1 * sl);                      \
            __half2 l1 = __floats2half2_rn(v2 * sl, v3 * sl);                      \
            *(uint2*)(WhB + row * (STR * 2) + kc4 * 8) =                           \
                make_uint2(*(unsigned*)&h0, *(unsigned*)&h1);                      \
            *(uint2*)(WlB + row * (STR * 2) + kc4 * 8) =                           \
                make_uint2(*(unsigned*)&l0, *(unsigned*)&l1);                      \
        }                                                                          \
        {                                                                          \
            int row = tid >> 2, seg = tid & 3;                                     \
            *(uint4*)(XhB + row * (STR * 2) + seg * 16) = xhr;                     \
            *(uint4*)(XlB + row * (STR * 2) + seg * 16) = xlr;                     \
        }                                                                          \
    }

    // ldmatrix lane addressing (round-8-validated):
    //  A x4: lanes 0-15 -> rows 0-15 @k, lanes 16-31 -> same rows @k+8
    //  B x2: lanes 0-7  -> rows j*8+0..7 @k, lanes 8-15 -> same @k+8
    const int aOff = (lane & 15) * (STR * 2) + ((lane & 16) ? 16 : 0);
    const int bOff = (lane & 7)  * (STR * 2) + ((lane & 8)  ? 16 : 0);

    LOAD_STAGE(0);

    for (int it = 0; it < ITERS; ++it) {
        const int buf = it & 1;
        STORE_STAGE(buf);
        __syncthreads();
        if (it + 1 < ITERS) LOAD_STAGE(it + 1);

        const unsigned aBaseH = (unsigned)__cvta_generic_to_shared(
            smem + WH_OFF + buf * 10240 + warp * 16 * (STR * 2) + aOff);
        const unsigned aBaseL = aBaseH + (WL_OFF - WH_OFF);
        const unsigned bBaseH = (unsigned)__cvta_generic_to_shared(
            smem + XH_OFF + buf * 5120 + bOff);
        const unsigned bBaseL = bBaseH + (XL_OFF - XH_OFF);

        #pragma unroll
        for (int kk = 0; kk < 2; ++kk) {
            unsigned ah0, ah1, ah2, ah3, al0, al1, al2, al3;
            asm volatile(
                "ldmatrix.sync.aligned.m8n8.x4.shared.b16 {%0,%1,%2,%3}, [%4];\n"
                : "=r"(ah0), "=r"(ah1), "=r"(ah2), "=r"(ah3)
                : "r"(aBaseH + kk * 32));
            asm volatile(
                "ldmatrix.sync.aligned.m8n8.x4.shared.b16 {%0,%1,%2,%3}, [%4];\n"
                : "=r"(al0), "=r"(al1), "=r"(al2), "=r"(al3)
                : "r"(aBaseL + kk * 32));
            #pragma unroll
            for (int j = 0; j < 8; ++j) {
                unsigned bh0, bh1, bl0, bl1;
                asm volatile(
                    "ldmatrix.sync.aligned.m8n8.x2.shared.b16 {%0,%1}, [%2];\n"
                    : "=r"(bh0), "=r"(bh1)
                    : "r"(bBaseH + j * (8 * STR * 2) + kk * 32));
                asm volatile(
                    "ldmatrix.sync.aligned.m8n8.x2.shared.b16 {%0,%1}, [%2];\n"
                    : "=r"(bl0), "=r"(bl1)
                    : "r"(bBaseL + j * (8 * STR * 2) + kk * 32));
                asm volatile(
                    "mma.sync.aligned.m16n8k16.row.col.f32.f16.f16.f32 "
                    "{%0,%1,%2,%3}, {%4,%5,%6,%7}, {%8,%9}, {%0,%1,%2,%3};\n"
                    : "+f"(acc[j][0]), "+f"(acc[j][1]), "+f"(acc[j][2]), "+f"(acc[j][3])
                    : "r"(ah0), "r"(ah1), "r"(ah2), "r"(ah3), "r"(bh0), "r"(bh1));
                asm volatile(
                    "mma.sync.aligned.m16n8k16.row.col.f32.f16.f16.f32 "
                    "{%0,%1,%2,%3}, {%4,%5,%6,%7}, {%8,%9}, {%0,%1,%2,%3};\n"
                    : "+f"(acc[j][0]), "+f"(acc[j][1]), "+f"(acc[j][2]), "+f"(acc[j][3])
                    : "r"(ah0), "r"(ah1), "r"(ah2), "r"(ah3), "r"(bl0), "r"(bl1));
                asm volatile(
                    "mma.sync.aligned.m16n8k16.row.col.f32.f16.f16.f32 "
                    "{%0,%1,%2,%3}, {%4,%5,%6,%7}, {%8,%9}, {%0,%1,%2,%3};\n"
                    : "+f"(acc[j][0]), "+f"(acc[j][1]), "+f"(acc[j][2]), "+f"(acc[j][3])
                    : "r"(al0), "r"(al1), "r"(al2), "r"(al3), "r"(bh0), "r"(bh1));
            }
        }
    }

    // ---- epilogue (round-8-validated D mapping) ----
    const int gid = lane >> 2;
    const int tg  = lane & 3;
    float* S = g_scratch + blockIdx.y * (M_DIM * N_DIM);
    const int nbase = bn * NTILE + warp * 16 + gid;
    #pragma unroll
    for (int j = 0; j < 8; ++j) {
        const int m0 = j * 8 + tg * 2;
        S[(m0    ) * N_DIM + nbase    ] = acc[j][0];
        S[(m0 + 1) * N_DIM + nbase    ] = acc[j][1];
        S[(m0    ) * N_DIM + nbase + 8] = acc[j][2];
        S[(m0 + 1) * N_DIM + nbase + 8] = acc[j][3];
    }
    #undef LOAD_STAGE
    #undef STORE_STAGE
}

// ---------------------------------------------------------------------------
// Kernel C: out (fp32 buffer) = fp32(bf16(sum_slabs * gx*gw/2^24 + bias[n]))
// (2^24 removes the 4096x boost applied to each operand side.)
// ---------------------------------------------------------------------------
__global__ void finalize_kernel(const float* __restrict__ g1,
                                const float* __restrict__ g2,
                                const float* __restrict__ bias,
                                float* __restrict__ out) {
    int idx = blockIdx.x * blockDim.x + threadIdx.x;
    if (idx >= M_DIM * N_DIM) return;
    const float g = g1[0] * g2[0] * (1.0f / 16777216.0f);
    const int n = idx & (N_DIM - 1);
    float s = 0.f;
    #pragma unroll
    for (int t = 0; t < KSPLIT; ++t)
        s += g_scratch[idx + t * (M_DIM * N_DIM)];
    float v = fmaf(s, g, bias[n]);
    out[idx] = __bfloat162float(__float2bfloat16(v));
}

// ---------------------------------------------------------------------------
// Inputs identified by element count (all distinct; byte-count fallback).
// ---------------------------------------------------------------------------
extern "C" void kernel_launch(void* const* d_in, const int* in_sizes, int n_in,
                              void* d_out, int out_size) {
    const int*   x    = nullptr;
    const float* xs   = nullptr;
    const int*   wgt  = nullptr;
    const float* wsc  = nullptr;
    const float* bias = nullptr;
    const float* gA   = nullptr;
    const float* gB   = nullptr;

    for (int pass = 0; pass < 2 && !wgt; ++pass) {
        const int mul = (pass == 0) ? 1 : 4;
        x = nullptr; xs = nullptr; wgt = nullptr; wsc = nullptr;
        bias = nullptr; gA = nullptr; gB = nullptr;
        for (int i = 0; i < n_in; ++i) {
            long sz = (long)in_sizes[i];
            if      (sz == (long)M_DIM * K_DIM * mul)          x    = (const int*)  d_in[i];
            else if (sz == (long)M_DIM * (K_DIM/KBLK) * mul)   xs   = (const float*)d_in[i];
            else if (sz == (long)N_DIM * K_DIM * mul)          wgt  = (const int*)  d_in[i];
            else if (sz == (long)N_DIM * (K_DIM/KBLK) * mul)   wsc  = (const float*)d_in[i];
            else if (sz == (long)N_DIM * mul)                  bias = (const float*)d_in[i];
            else if (sz == 1 * mul) { if (!gA) gA = (const float*)d_in[i];
                                      else     gB = (const float*)d_in[i]; }
        }
    }

    cudaFuncSetAttribute(gemm_kernel,
                         cudaFuncAttributeMaxDynamicSharedMemorySize, SMEM_BYTES);

    prep_kernel<<<(M_DIM * K_DIM / 4) / THREADS, THREADS>>>(x, xs);
    gemm_kernel<<<dim3(N_DIM / NTILE, KSPLIT), THREADS, SMEM_BYTES>>>(wgt, wsc);
    finalize_kernel<<<(M_DIM * N_DIM) / 256, 256>>>(gA, gB, bias,
                                                    (float*)d_out);
}